// round 2
// baseline (speedup 1.0000x reference)
#include <cuda_runtime.h>
#include <cuda_bf16.h>

#define B_ROWS 16384
#define N_DIM  1000
#define BM 128
#define BN 128
#define BK 8
#define TM 8
#define TN 8

// Scratch for PM = P / M[:,None]  (4 MB, static device allocation -> allowed)
__device__ float g_PM[N_DIM * N_DIM];

__global__ void pm_kernel(const float* __restrict__ P, const float* __restrict__ M) {
    int idx = blockIdx.x * blockDim.x + threadIdx.x;
    if (idx < N_DIM * N_DIM) {
        int n = idx / N_DIM;
        g_PM[idx] = P[idx] / M[n];
    }
}

__global__ void zero_kernel(float* __restrict__ out) {
    int idx = blockIdx.x * blockDim.x + threadIdx.x;
    if (idx < B_ROWS) out[idx] = 0.0f;
}

// losses[b] = (1/N) * sum_{n,k} Y[b,n] * PM[n,k] * Y[b,k]
// Tiled as GEMM C = Y @ PM^T fused with epilogue rowsum(Y .* C).
__global__ __launch_bounds__(256) void qf_kernel(const float* __restrict__ Y,
                                                 float* __restrict__ out) {
    __shared__ float Ys[BK][BM];   // Y tile, transposed:  Ys[k][m]
    __shared__ float Ps[BK][BN];   // PM tile, transposed: Ps[k][n]

    const int tid = threadIdx.x;
    const int tx  = tid & 15;   // n direction (16 threads * TN=8 -> 128)
    const int ty  = tid >> 4;   // m direction (16 threads * TM=8 -> 128)
    const int rowBase = blockIdx.y * BM;
    const int colBase = blockIdx.x * BN;

    float acc[TM][TN];
    #pragma unroll
    for (int i = 0; i < TM; i++)
        #pragma unroll
        for (int j = 0; j < TN; j++) acc[i][j] = 0.0f;

    // cooperative-load indices: 64 rows x 4 float2 per pass, 2 passes
    const int lrow = tid >> 2;         // 0..63
    const int lk   = (tid & 3) * 2;    // 0,2,4,6

    for (int k0 = 0; k0 < N_DIM; k0 += BK) {
        // --- Y tile: rows [rowBase, rowBase+128), cols [k0, k0+8) ---
        #pragma unroll
        for (int h = 0; h < 2; h++) {
            int r = lrow + h * 64;
            const float2 v = *reinterpret_cast<const float2*>(
                &Y[(size_t)(rowBase + r) * N_DIM + k0 + lk]);
            Ys[lk    ][r] = v.x;
            Ys[lk + 1][r] = v.y;
        }
        // --- PM tile: rows (n) [colBase, colBase+128), cols [k0, k0+8) ---
        #pragma unroll
        for (int h = 0; h < 2; h++) {
            int n  = lrow + h * 64;
            int gn = colBase + n;
            float2 v = make_float2(0.0f, 0.0f);
            if (gn < N_DIM)
                v = *reinterpret_cast<const float2*>(
                    &g_PM[(size_t)gn * N_DIM + k0 + lk]);
            Ps[lk    ][n] = v.x;
            Ps[lk + 1][n] = v.y;
        }
        __syncthreads();

        #pragma unroll
        for (int kk = 0; kk < BK; kk++) {
            float a[TM], b[TN];
            #pragma unroll
            for (int i = 0; i < TM; i++) a[i] = Ys[kk][ty * TM + i];
            #pragma unroll
            for (int j = 0; j < TN; j++) b[j] = Ps[kk][tx * TN + j];
            #pragma unroll
            for (int i = 0; i < TM; i++)
                #pragma unroll
                for (int j = 0; j < TN; j++)
                    acc[i][j] += a[i] * b[j];
        }
        __syncthreads();
    }

    // Epilogue: partial[b] = sum_j acc[i][j] * Y[b, col_j]; reduce over tx; atomicAdd.
    const float invN = 1.0f / (float)N_DIM;
    #pragma unroll
    for (int i = 0; i < TM; i++) {
        const int row = rowBase + ty * TM + i;
        float partial = 0.0f;
        #pragma unroll
        for (int j = 0; j < TN; j++) {
            const int col = colBase + tx * TN + j;
            if (col < N_DIM)
                partial += acc[i][j] * Y[(size_t)row * N_DIM + col];
        }
        // reduce across the 16 tx lanes (xor offsets < 16 stay inside each half-warp)
        #pragma unroll
        for (int off = 8; off >= 1; off >>= 1)
            partial += __shfl_xor_sync(0xffffffffu, partial, off);
        if (tx == 0)
            atomicAdd(&out[row], partial * invN);
    }
}

extern "C" void kernel_launch(void* const* d_in, const int* in_sizes, int n_in,
                              void* d_out, int out_size) {
    const float* y_pred = (const float*)d_in[0];
    // d_in[1] = y_true (unused by the loss)
    const float* P = (const float*)d_in[2];
    const float* M = (const float*)d_in[3];
    float* out = (float*)d_out;

    (void)in_sizes; (void)n_in; (void)out_size;

    pm_kernel<<<(N_DIM * N_DIM + 255) / 256, 256>>>(P, M);
    zero_kernel<<<(B_ROWS + 255) / 256, 256>>>(out);

    dim3 grid((N_DIM + BN - 1) / BN, B_ROWS / BM);  // (8, 128)
    qf_kernel<<<grid, 256>>>(y_pred, out);
}